// round 12
// baseline (speedup 1.0000x reference)
#include <cuda_runtime.h>
#include <cuda_bf16.h>

__device__ int g_is_cyclic;   // written by check kernel; read after griddepsync

// Check node: fires PDL trigger at entry so the scan kernel launches and runs
// its sum phase concurrently. 1 block x 1024 threads.
__global__ void __launch_bounds__(1024) check_cyclic_kernel(
    const int* __restrict__ mul, int n)
{
    cudaTriggerProgrammaticLaunchCompletion();
    __shared__ int ok;
    if (threadIdx.x == 0) ok = 1;
    __syncthreads();
    int total = n * n;
    for (int i = threadIdx.x; i < total; i += 1024) {
        int a = i / n;
        int b = i - a * n;
        int e = a + b;
        if (e >= n) e -= n;
        if (__ldg(mul + i) != e) ok = 0;   // benign race: all writers store 0
    }
    __syncthreads();
    if (threadIdx.x == 0) g_is_cyclic = ok;
}

#define TPB 128  // 4 warps/block -> 1024 blocks, one balanced wave

// Write one-hot row of n floats as float4 stores (requires n%4==0; row base
// out+r*n is then 16B-aligned for every r).
__device__ __forceinline__ void write_onehot_vec4(float* __restrict__ orow,
                                                  int n, int s, float hi, float lo,
                                                  int lane)
{
    int nq = n >> 2;
    for (int q = lane; q < nq; q += 32) {
        int c = q << 2;
        float4 v;
        v.x = (c + 0 == s) ? hi : lo;
        v.y = (c + 1 == s) ? hi : lo;
        v.z = (c + 2 == s) ? hi : lo;
        v.w = (c + 3 == s) ? hi : lo;
        reinterpret_cast<float4*>(orow)[q] = v;
    }
}

__device__ __forceinline__ void write_onehot_scalar(float* __restrict__ orow,
                                                    int n, int s, float hi, float lo,
                                                    int lane)
{
    for (int i = lane; i < n; i += 32)
        orow[i] = (i == s) ? hi : lo;
}

__global__ void __launch_bounds__(TPB) a5_scan_kernel(
    const float* __restrict__ scale_p,
    const int* __restrict__ ids,
    const int* __restrict__ mul,
    float* __restrict__ out,
    int n, int b_rows, int t_len, int total_warps)
{
    int lane  = threadIdx.x & 31;
    int warp0 = (int)((blockIdx.x * (unsigned)TPB + threadIdx.x) >> 5);

    int nvec = t_len >> 2;
    bool vec_ok = ((t_len & 3) == 0);
    bool n4 = ((n & 3) == 0);
    bool single_pass = vec_ok && (b_rows <= 2 * total_warps);

    float sc = __ldg(scale_p);
    float hi = 10.0f * sc;
    float lo = -10.0f * sc;

    if (single_pass) {
        // ---- Overlapped path: sums first, verdict after griddepsync ----
        int r  = warp0;
        int r2 = warp0 + total_warps;
        bool have1 = (r < b_rows);
        bool have2 = (r2 < b_rows);

        int sa = 0, sb = 0;
        if (have1) {
            const int4* p0 = (const int4*)(ids + (long long)r * t_len);
            const int4* p1 = (const int4*)(ids + (long long)(have2 ? r2 : r) * t_len);
            int s0 = 0, s1 = 0;
            #pragma unroll 8
            for (int j = lane; j < nvec; j += 32) {
                int4 a = __ldcs(p0 + j);     // streaming: read once, evict-first
                int4 b = __ldcs(p1 + j);
                s0 += a.x + a.y + a.z + a.w;
                s1 += b.x + b.y + b.z + b.w;
            }
            #pragma unroll
            for (int d = 16; d; d >>= 1) {
                s0 += __shfl_xor_sync(0xffffffffu, s0, d);
                s1 += __shfl_xor_sync(0xffffffffu, s1, d);
            }
            sa = s0 % n;
            sb = s1 % n;
        }

        cudaGridDependencySynchronize();   // check kernel done + visible
        bool cyclic = (g_is_cyclic != 0);

        if (!have1) return;
        if (cyclic) {
            float* o0 = out + (long long)r * n;
            if (n4) write_onehot_vec4(o0, n, sa, hi, lo, lane);
            else    write_onehot_scalar(o0, n, sa, hi, lo, lane);
            if (have2) {
                float* o1 = out + (long long)r2 * n;
                if (n4) write_onehot_vec4(o1, n, sb, hi, lo, lane);
                else    write_onehot_scalar(o1, n, sb, hi, lo, lane);
            }
        } else {
            // Non-cyclic fallback: ordered group product per row
            for (int k = 0; k < 2; k++) {
                int rr = (k == 0) ? r : r2;
                if (k == 1 && !have2) break;
                const int* row = ids + (long long)rr * t_len;
                int s;
                if ((t_len & 31) == 0) {
                    int chunk = t_len >> 5;
                    const int* base = row + lane * chunk;
                    int q = 0;                       // identity
                    for (int j = 0; j < chunk; j++) {
                        int x = __ldg(base + j);
                        q = __ldg(mul + x * n + q);  // q = x . q
                    }
                    #pragma unroll
                    for (int d = 1; d < 32; d <<= 1) {
                        int t = __shfl_up_sync(0xffffffffu, q, d);
                        if (lane >= d) q = __ldg(mul + q * n + t);
                    }
                    s = __shfl_sync(0xffffffffu, q, 31);
                } else {
                    int q = 0;
                    if (lane == 0)
                        for (int j = 0; j < t_len; j++)
                            q = __ldg(mul + __ldg(row + j) * n + q);
                    s = __shfl_sync(0xffffffffu, q, 0);
                }
                write_onehot_scalar(out + (long long)rr * n, n, s, hi, lo, lane);
            }
        }
    } else {
        // ---- Generic path: resolve verdict up front, then grid-stride ----
        cudaGridDependencySynchronize();
        bool cyclic = (g_is_cyclic != 0);

        for (int r = warp0; r < b_rows; r += 2 * total_warps) {
            int r2 = r + total_warps;
            bool have2 = (r2 < b_rows);

            if (cyclic && vec_ok) {
                const int4* p0 = (const int4*)(ids + (long long)r * t_len);
                const int4* p1 = (const int4*)(ids + (long long)(have2 ? r2 : r) * t_len);
                int s0 = 0, s1 = 0;
                #pragma unroll 8
                for (int j = lane; j < nvec; j += 32) {
                    int4 a = __ldcs(p0 + j);
                    int4 b = __ldcs(p1 + j);
                    s0 += a.x + a.y + a.z + a.w;
                    s1 += b.x + b.y + b.z + b.w;
                }
                #pragma unroll
                for (int d = 16; d; d >>= 1) {
                    s0 += __shfl_xor_sync(0xffffffffu, s0, d);
                    s1 += __shfl_xor_sync(0xffffffffu, s1, d);
                }
                int sa = s0 % n;
                int sb = s1 % n;
                float* o0 = out + (long long)r * n;
                if (n4) write_onehot_vec4(o0, n, sa, hi, lo, lane);
                else    write_onehot_scalar(o0, n, sa, hi, lo, lane);
                if (have2) {
                    float* o1 = out + (long long)r2 * n;
                    if (n4) write_onehot_vec4(o1, n, sb, hi, lo, lane);
                    else    write_onehot_scalar(o1, n, sb, hi, lo, lane);
                }
            } else {
                for (int k = 0; k < 2; k++) {
                    int rr = (k == 0) ? r : r2;
                    if (k == 1 && !have2) break;
                    const int* row = ids + (long long)rr * t_len;
                    int s;
                    if ((t_len & 31) == 0) {
                        int chunk = t_len >> 5;
                        const int* base = row + lane * chunk;
                        int q = 0;
                        for (int j = 0; j < chunk; j++) {
                            int x = __ldg(base + j);
                            q = __ldg(mul + x * n + q);
                        }
                        #pragma unroll
                        for (int d = 1; d < 32; d <<= 1) {
                            int t = __shfl_up_sync(0xffffffffu, q, d);
                            if (lane >= d) q = __ldg(mul + q * n + t);
                        }
                        s = __shfl_sync(0xffffffffu, q, 31);
                    } else {
                        int q = 0;
                        if (lane == 0)
                            for (int j = 0; j < t_len; j++)
                                q = __ldg(mul + __ldg(row + j) * n + q);
                        s = __shfl_sync(0xffffffffu, q, 0);
                    }
                    write_onehot_scalar(out + (long long)rr * n, n, s, hi, lo, lane);
                }
            }
        }
    }
}

extern "C" void kernel_launch(void* const* d_in, const int* in_sizes, int n_in,
                              void* d_out, int out_size) {
    const float* scale = (const float*)d_in[0];
    const int*   ids   = (const int*)d_in[1];
    const int*   mul   = (const int*)d_in[2];
    float*       out   = (float*)d_out;

    int mn = in_sizes[2];
    int n = 1;
    while (n * n < mn) n++;

    int b_rows = out_size / n;              // 8192
    int t_len  = in_sizes[1] / b_rows;      // 2048

    check_cyclic_kernel<<<1, 1024>>>(mul, n);

    // 2 rows per warp -> 8 rows per 4-warp block -> 1024 blocks, one wave.
    const int warps_per_block = TPB / 32;
    int blocks = (b_rows + 2 * warps_per_block - 1) / (2 * warps_per_block);
    int total_warps = blocks * warps_per_block;

    // PDL: scan starts while check kernel runs; griddepsync resolves verdict.
    cudaLaunchConfig_t cfg = {};
    cfg.gridDim  = dim3((unsigned)blocks, 1, 1);
    cfg.blockDim = dim3(TPB, 1, 1);
    cfg.dynamicSmemBytes = 0;
    cfg.stream = 0;
    cudaLaunchAttribute attr[1];
    attr[0].id = cudaLaunchAttributeProgrammaticStreamSerialization;
    attr[0].val.programmaticStreamSerializationAllowed = 1;
    cfg.attrs = attr;
    cfg.numAttrs = 1;
    cudaLaunchKernelEx(&cfg, a5_scan_kernel, scale, ids, mul, out,
                       n, b_rows, t_len, total_warps);
}